// round 11
// baseline (speedup 1.0000x reference)
#include <cuda_runtime.h>

#define NSC       4096
#define NT        14
#define THREADS   512
#define PAD(f)    ((f) + ((f) >> 3))
#define RSQ2      0.70710678118654752f
// shared layout (float2 units): Tb[0,1024) | Y0[1024,3328) | Y1[3328,5632) | R0+R1 [5632,7680)
// R0 = 2048 floats, R1 = 2048 floats  ->  total 7680 float2 = 61440 bytes
#define SMEM_BYTES 61440

__constant__ float c_w[NT] = {0.f, 0.f, 0.f, 1.f/9, 2.f/9, 3.f/9, 4.f/9, 5.f/9,
                              6.f/9, 7.f/9, 8.f/9, 1.f, 1.f, 1.f};

__device__ __forceinline__ float2 cadd(float2 a, float2 b) { return make_float2(a.x + b.x, a.y + b.y); }
__device__ __forceinline__ float2 csub(float2 a, float2 b) { return make_float2(a.x - b.x, a.y - b.y); }
__device__ __forceinline__ float2 cmul(float2 a, float2 b) {
    return make_float2(a.x * b.x - a.y * b.y, a.x * b.y + a.y * b.x);
}

// Forward radix-8 DIF stage (L=8h). Output k twiddled by conj(Tb[j*str])^k.
__device__ __forceinline__ void fwd8(float2* __restrict__ A, const float2* __restrict__ Tb,
                                     int q, int h, int str) {
    int j    = q & (h - 1);
    int base = ((q - j) << 3) + j;
    float2 t0 = A[PAD(base)],         t1 = A[PAD(base + h)];
    float2 t2 = A[PAD(base + 2 * h)], t3 = A[PAD(base + 3 * h)];
    float2 t4 = A[PAD(base + 4 * h)], t5 = A[PAD(base + 5 * h)];
    float2 t6 = A[PAD(base + 6 * h)], t7 = A[PAD(base + 7 * h)];

    float2 a0 = cadd(t0, t4), a1 = cadd(t1, t5), a2 = cadd(t2, t6), a3 = cadd(t3, t7);
    float2 b0 = csub(t0, t4), b1 = csub(t1, t5), b2 = csub(t2, t6), b3 = csub(t3, t7);
    float2 c0 = cadd(a0, a2), c1 = csub(a0, a2), c2 = cadd(a1, a3), c3 = csub(a1, a3);
    float2 X0 = cadd(c0, c2), X4 = csub(c0, c2);
    float2 X2 = make_float2(c1.x + c3.y, c1.y - c3.x);
    float2 X6 = make_float2(c1.x - c3.y, c1.y + c3.x);
    float2 d0 = b0;
    float2 d1 = make_float2(RSQ2 * (b1.x + b1.y), RSQ2 * (b1.y - b1.x));
    float2 d2 = make_float2(b2.y, -b2.x);
    float2 d3 = make_float2(RSQ2 * (b3.y - b3.x), RSQ2 * (-(b3.x + b3.y)));
    float2 e0 = cadd(d0, d2), ee1 = csub(d0, d2), e2 = cadd(d1, d3), e3 = csub(d1, d3);
    float2 X1 = cadd(e0, e2), X5 = csub(e0, e2);
    float2 X3 = make_float2(ee1.x + e3.y, ee1.y - e3.x);
    float2 X7 = make_float2(ee1.x - e3.y, ee1.y + e3.x);

    float2 w1 = Tb[j * str]; w1.y = -w1.y;
    float2 w2 = cmul(w1, w1);
    float2 w3 = cmul(w2, w1);
    float2 w4 = cmul(w2, w2);
    float2 w5 = cmul(w4, w1);
    float2 w6 = cmul(w4, w2);
    float2 w7 = cmul(w4, w3);
    A[PAD(base)]         = X0;
    A[PAD(base + h)]     = cmul(X1, w1);
    A[PAD(base + 2 * h)] = cmul(X2, w2);
    A[PAD(base + 3 * h)] = cmul(X3, w3);
    A[PAD(base + 4 * h)] = cmul(X4, w4);
    A[PAD(base + 5 * h)] = cmul(X5, w5);
    A[PAD(base + 6 * h)] = cmul(X6, w6);
    A[PAD(base + 7 * h)] = cmul(X7, w7);
}

// Inverse radix-8 DIT stage: twiddle inputs by Tb[j*str]^k, then IDFT8.
// If LAST, write REAL PART ONLY to plain-float array R (h=256 path).
template <bool LAST>
__device__ __forceinline__ void inv8(float2* __restrict__ A, float* __restrict__ R,
                                     const float2* __restrict__ Tb,
                                     int q, int h, int str) {
    int j    = q & (h - 1);
    int base = ((q - j) << 3) + j;
    float2 w1 = Tb[j * str];
    float2 w2 = cmul(w1, w1);
    float2 w3 = cmul(w2, w1);
    float2 w4 = cmul(w2, w2);
    float2 w5 = cmul(w4, w1);
    float2 w6 = cmul(w4, w2);
    float2 w7 = cmul(w4, w3);
    float2 t0 = A[PAD(base)];
    float2 t1 = cmul(A[PAD(base + h)],     w1);
    float2 t2 = cmul(A[PAD(base + 2 * h)], w2);
    float2 t3 = cmul(A[PAD(base + 3 * h)], w3);
    float2 t4 = cmul(A[PAD(base + 4 * h)], w4);
    float2 t5 = cmul(A[PAD(base + 5 * h)], w5);
    float2 t6 = cmul(A[PAD(base + 6 * h)], w6);
    float2 t7 = cmul(A[PAD(base + 7 * h)], w7);

    float2 a0 = cadd(t0, t4), a1 = cadd(t1, t5), a2 = cadd(t2, t6), a3 = cadd(t3, t7);
    float2 b0 = csub(t0, t4), b1 = csub(t1, t5), b2 = csub(t2, t6), b3 = csub(t3, t7);
    float2 c0 = cadd(a0, a2), c1 = csub(a0, a2), c2 = cadd(a1, a3), c3 = csub(a1, a3);
    float2 X0 = cadd(c0, c2), X4 = csub(c0, c2);
    float2 X2 = make_float2(c1.x - c3.y, c1.y + c3.x);
    float2 X6 = make_float2(c1.x + c3.y, c1.y - c3.x);
    float2 d0 = b0;
    float2 d1 = make_float2(RSQ2 * (b1.x - b1.y), RSQ2 * (b1.y + b1.x));
    float2 d2 = make_float2(-b2.y, b2.x);
    float2 d3 = make_float2(RSQ2 * (-(b3.x + b3.y)), RSQ2 * (b3.x - b3.y));
    float2 e0 = cadd(d0, d2), ee1 = csub(d0, d2), e2 = cadd(d1, d3), e3 = csub(d1, d3);
    float2 X1 = cadd(e0, e2), X5 = csub(e0, e2);
    float2 X3 = make_float2(ee1.x - e3.y, ee1.y + e3.x);
    float2 X7 = make_float2(ee1.x + e3.y, ee1.y - e3.x);

    if (LAST) {
        R[base]         = X0.x;
        R[base + h]     = X1.x;
        R[base + 2 * h] = X2.x;
        R[base + 3 * h] = X3.x;
        R[base + 4 * h] = X4.x;
        R[base + 5 * h] = X5.x;
        R[base + 6 * h] = X6.x;
        R[base + 7 * h] = X7.x;
    } else {
        A[PAD(base)]         = X0;
        A[PAD(base + h)]     = X1;
        A[PAD(base + 2 * h)] = X2;
        A[PAD(base + 3 * h)] = X3;
        A[PAD(base + 4 * h)] = X4;
        A[PAD(base + 5 * h)] = X5;
        A[PAD(base + 6 * h)] = X6;
        A[PAD(base + 7 * h)] = X7;
    }
}

__global__ __launch_bounds__(THREADS) void tdi_kernel(const float* __restrict__ pr,
                                                      const float* __restrict__ pi,
                                                      float4* __restrict__ out,   // real parts, [b][t][sc]
                                                      long long n0, long long n1,
                                                      long long cap_f4)
{
    extern __shared__ float2 sh[];
    float2* Tb = sh;
    float2* Y0 = sh + 1024;
    float2* Y1 = sh + 3328;
    float*  R0 = (float*)(sh + 5632);   // 2048 floats
    float*  R1 = R0 + 2048;             // 2048 floats (ends at float2 idx 7680 = 61440 B)

    const int tid = threadIdx.x;
    const int b   = blockIdx.x;
    const long long base = (long long)b * 4096;

    for (int m = tid; m < 1024; m += THREADS) {
        float s, c;
        __sincosf((float)m * 3.0679615757712823e-3f, &s, &c);   // 2*pi/2048
        Tb[m] = make_float2(c, s);
    }
    for (int n = tid; n < 2048; n += THREADS) {
        long long i0 = base + n;
        long long i1 = base + n + 2048;
        float r0 = (i0 < n0) ? pr[i0] : 0.0f;
        float m0 = (i0 < n1) ? pi[i0] : 0.0f;
        float r1 = (i1 < n0) ? pr[i1] : 0.0f;
        float m1 = (i1 < n1) ? pi[i1] : 0.0f;
        Y0[PAD(n)] = make_float2(r0, m0);
        Y1[PAD(n)] = make_float2(r1, m1);
    }
    __syncthreads();

    const int q = tid & 255;
    float2* Aq  = (tid >> 8) ? Y1 : Y0;
    float*  Rq  = (tid >> 8) ? R1 : R0;

    // forward radix-8 DIF: h = 256, 32, 4
    fwd8(Aq, Tb, q, 256, 1);  __syncthreads();
    fwd8(Aq, Tb, q, 32,  8);  __syncthreads();
    fwd8(Aq, Tb, q, 4,   64); __syncthreads();

    // fused middle: forward radix-4 (L=4) + pointwise w[k]/2048 + inverse radix-4
    {
        int m = tid;
        int revm = ((m & 7) << 6) | (m & 56) | (m >> 6);   // octal-digit reverse
        float sn, cs;
        __sincosf((float)revm * 1.5339807878856412e-3f, &sn, &cs);   // 2*pi/4096
        float2 w0 = make_float2(cs * (1.0f / 2048.0f), sn * (1.0f / 2048.0f));
        float2 wA = make_float2(RSQ2 * (w0.x - w0.y), RSQ2 * (w0.x + w0.y));
        float2 wB = make_float2(w0.y, -w0.x);
        float2 wC = make_float2(RSQ2 * (w0.x + w0.y), RSQ2 * (w0.y - w0.x));
        int p = 4 * m;
        #pragma unroll
        for (int s = 0; s < 2; s++) {
            float2* A = s ? Y1 : Y0;
            float2 t0 = A[PAD(p)],     t1 = A[PAD(p + 1)];
            float2 t2 = A[PAD(p + 2)], t3 = A[PAD(p + 3)];
            float2 a = cadd(t0, t2), bb = csub(t0, t2);
            float2 c = cadd(t1, t3), d  = csub(t1, t3);
            float2 F0 = cadd(a, c);
            float2 F1 = make_float2(bb.x + d.y, bb.y - d.x);
            float2 F2 = csub(a, c);
            float2 F3 = make_float2(bb.x - d.y, bb.y + d.x);
            float2 G0 = cmul(F0, w0), G1 = cmul(F1, wA);
            float2 G2 = cmul(F2, wB), G3 = cmul(F3, wC);
            float2 ap = cadd(G0, G2), bp = csub(G0, G2);
            float2 cp = cadd(G1, G3), dp = csub(G1, G3);
            A[PAD(p)]     = cadd(ap, cp);
            A[PAD(p + 2)] = csub(ap, cp);
            A[PAD(p + 1)] = make_float2(bp.x - dp.y, bp.y + dp.x);
            A[PAD(p + 3)] = make_float2(bp.x + dp.y, bp.y - dp.x);
        }
    }
    __syncthreads();

    // inverse radix-8 DIT: h = 4, 32, 256 (last writes real-only to R)
    inv8<false>(Aq, Rq, Tb, q, 4,   64); __syncthreads();
    inv8<false>(Aq, Rq, Tb, q, 32,  8);  __syncthreads();
    inv8<true> (Aq, Rq, Tb, q, 256, 1);  __syncthreads();

    // output: real parts, [b][t][sc]; one float4 covers sc {4u, 4u+1, 4u+2, 4u+3}
    const long long obf4 = (long long)b * (NT * NSC / 4);
    const bool ok = (obf4 + (long long)NT * (NSC / 4)) <= cap_f4
                 && (base + 4096) <= n0;
    for (int u = tid; u < 1024; u += THREADS) {
        int ra = 2 * u, rb = 2 * u + 1;          // odd-pair indices
        if (ok) {
            float ea0 = pr[base + ra], ea1 = pr[base + ra + 2048];
            float eb0 = pr[base + rb], eb1 = pr[base + rb + 2048];
            float oa0 = R0[ra], oa1 = R1[ra];
            float ob0 = R0[rb], ob1 = R1[rb];
            #pragma unroll
            for (int t = 0; t < NT; t++) {
                float w = c_w[t];
                float4 v;
                v.x = ea0 + (ea1 - ea0) * w;
                v.y = oa0 + (oa1 - oa0) * w;
                v.z = eb0 + (eb1 - eb0) * w;
                v.w = ob0 + (ob1 - ob0) * w;
                out[obf4 + (long long)t * (NSC / 4) + u] = v;
            }
        } else {
            float ea0 = (base + ra < n0) ? pr[base + ra] : 0.0f;
            float ea1 = (base + ra + 2048 < n0) ? pr[base + ra + 2048] : 0.0f;
            float eb0 = (base + rb < n0) ? pr[base + rb] : 0.0f;
            float eb1 = (base + rb + 2048 < n0) ? pr[base + rb + 2048] : 0.0f;
            float oa0 = R0[ra], oa1 = R1[ra];
            float ob0 = R0[rb], ob1 = R1[rb];
            #pragma unroll
            for (int t = 0; t < NT; t++) {
                float w = c_w[t];
                long long f4 = obf4 + (long long)t * (NSC / 4) + u;
                if (f4 < cap_f4) {
                    float4 v;
                    v.x = ea0 + (ea1 - ea0) * w;
                    v.y = oa0 + (oa1 - oa0) * w;
                    v.z = eb0 + (eb1 - eb0) * w;
                    v.w = ob0 + (ob1 - ob0) * w;
                    out[f4] = v;
                }
            }
        }
    }
}

extern "C" void kernel_launch(void* const* d_in, const int* in_sizes, int n_in,
                              void* d_out, int out_size) {
    const float* pr = (const float*)d_in[0];
    const int ilast = (n_in > 1) ? (n_in - 1) : 0;
    const float* pi = (const float*)d_in[ilast];

    const long long n0 = (long long)in_sizes[0];
    const long long n1 = (long long)in_sizes[ilast];

    long long B = n0 / 4096;
    long long B_cap = (long long)out_size / ((long long)NT * NSC);
    if (B_cap < B) B = B_cap;
    if (B < 1) B = 1;
    if (B > 65535) B = 65535;

    const long long cap_f4 = (long long)out_size / 4;

    static bool attr_done = false;
    if (!attr_done) {
        cudaFuncSetAttribute(tdi_kernel, cudaFuncAttributeMaxDynamicSharedMemorySize, SMEM_BYTES);
        attr_done = true;
    }
    tdi_kernel<<<(int)B, THREADS, SMEM_BYTES>>>(pr, pi, (float4*)d_out, n0, n1, cap_f4);
}

// round 12
// speedup vs baseline: 1.0204x; 1.0204x over previous
#include <cuda_runtime.h>

#define NSC       4096
#define NT        14
#define THREADS   256
#define PAD(f)    ((f) + ((f) >> 3))
#define RSQ2      0.70710678118654752f
// shared (float2 units): Tb[0,256) | Y0[256,2560) | Y1[2560,4864) | R0 [4864,5888) | R1 [5888,6912)
// total 6912 float2 = 55296 bytes  (fits 4 CTAs/SM: 4*54KB = 216KB < 227KB)
#define SMEM_BYTES 55296

__constant__ float c_w[NT] = {0.f, 0.f, 0.f, 1.f/9, 2.f/9, 3.f/9, 4.f/9, 5.f/9,
                              6.f/9, 7.f/9, 8.f/9, 1.f, 1.f, 1.f};

__device__ __forceinline__ float2 cadd(float2 a, float2 b) { return make_float2(a.x + b.x, a.y + b.y); }
__device__ __forceinline__ float2 csub(float2 a, float2 b) { return make_float2(a.x - b.x, a.y - b.y); }
__device__ __forceinline__ float2 cmul(float2 a, float2 b) {
    return make_float2(a.x * b.x - a.y * b.y, a.x * b.y + a.y * b.x);
}

// Forward radix-8 DIF stage (L=8h). Twiddle index j*str <= 255 always.
__device__ __forceinline__ void fwd8(float2* __restrict__ A, const float2* __restrict__ Tb,
                                     int q, int h, int str) {
    int j    = q & (h - 1);
    int base = ((q - j) << 3) + j;
    float2 t0 = A[PAD(base)],         t1 = A[PAD(base + h)];
    float2 t2 = A[PAD(base + 2 * h)], t3 = A[PAD(base + 3 * h)];
    float2 t4 = A[PAD(base + 4 * h)], t5 = A[PAD(base + 5 * h)];
    float2 t6 = A[PAD(base + 6 * h)], t7 = A[PAD(base + 7 * h)];

    float2 a0 = cadd(t0, t4), a1 = cadd(t1, t5), a2 = cadd(t2, t6), a3 = cadd(t3, t7);
    float2 b0 = csub(t0, t4), b1 = csub(t1, t5), b2 = csub(t2, t6), b3 = csub(t3, t7);
    float2 c0 = cadd(a0, a2), c1 = csub(a0, a2), c2 = cadd(a1, a3), c3 = csub(a1, a3);
    float2 X0 = cadd(c0, c2), X4 = csub(c0, c2);
    float2 X2 = make_float2(c1.x + c3.y, c1.y - c3.x);
    float2 X6 = make_float2(c1.x - c3.y, c1.y + c3.x);
    float2 d0 = b0;
    float2 d1 = make_float2(RSQ2 * (b1.x + b1.y), RSQ2 * (b1.y - b1.x));
    float2 d2 = make_float2(b2.y, -b2.x);
    float2 d3 = make_float2(RSQ2 * (b3.y - b3.x), RSQ2 * (-(b3.x + b3.y)));
    float2 e0 = cadd(d0, d2), ee1 = csub(d0, d2), e2 = cadd(d1, d3), e3 = csub(d1, d3);
    float2 X1 = cadd(e0, e2), X5 = csub(e0, e2);
    float2 X3 = make_float2(ee1.x + e3.y, ee1.y - e3.x);
    float2 X7 = make_float2(ee1.x - e3.y, ee1.y + e3.x);

    float2 w1 = Tb[j * str]; w1.y = -w1.y;
    float2 w2 = cmul(w1, w1);
    float2 w3 = cmul(w2, w1);
    float2 w4 = cmul(w2, w2);
    float2 w5 = cmul(w4, w1);
    float2 w6 = cmul(w4, w2);
    float2 w7 = cmul(w4, w3);
    A[PAD(base)]         = X0;
    A[PAD(base + h)]     = cmul(X1, w1);
    A[PAD(base + 2 * h)] = cmul(X2, w2);
    A[PAD(base + 3 * h)] = cmul(X3, w3);
    A[PAD(base + 4 * h)] = cmul(X4, w4);
    A[PAD(base + 5 * h)] = cmul(X5, w5);
    A[PAD(base + 6 * h)] = cmul(X6, w6);
    A[PAD(base + 7 * h)] = cmul(X7, w7);
}

// Inverse radix-8 DIT stage. If LAST, write real parts only to R.
template <bool LAST>
__device__ __forceinline__ void inv8(float2* __restrict__ A, float* __restrict__ R,
                                     const float2* __restrict__ Tb,
                                     int q, int h, int str) {
    int j    = q & (h - 1);
    int base = ((q - j) << 3) + j;
    float2 w1 = Tb[j * str];
    float2 w2 = cmul(w1, w1);
    float2 w3 = cmul(w2, w1);
    float2 w4 = cmul(w2, w2);
    float2 w5 = cmul(w4, w1);
    float2 w6 = cmul(w4, w2);
    float2 w7 = cmul(w4, w3);
    float2 t0 = A[PAD(base)];
    float2 t1 = cmul(A[PAD(base + h)],     w1);
    float2 t2 = cmul(A[PAD(base + 2 * h)], w2);
    float2 t3 = cmul(A[PAD(base + 3 * h)], w3);
    float2 t4 = cmul(A[PAD(base + 4 * h)], w4);
    float2 t5 = cmul(A[PAD(base + 5 * h)], w5);
    float2 t6 = cmul(A[PAD(base + 6 * h)], w6);
    float2 t7 = cmul(A[PAD(base + 7 * h)], w7);

    float2 a0 = cadd(t0, t4), a1 = cadd(t1, t5), a2 = cadd(t2, t6), a3 = cadd(t3, t7);
    float2 b0 = csub(t0, t4), b1 = csub(t1, t5), b2 = csub(t2, t6), b3 = csub(t3, t7);
    float2 c0 = cadd(a0, a2), c1 = csub(a0, a2), c2 = cadd(a1, a3), c3 = csub(a1, a3);
    float2 X0 = cadd(c0, c2), X4 = csub(c0, c2);
    float2 X2 = make_float2(c1.x - c3.y, c1.y + c3.x);
    float2 X6 = make_float2(c1.x + c3.y, c1.y - c3.x);
    float2 d0 = b0;
    float2 d1 = make_float2(RSQ2 * (b1.x - b1.y), RSQ2 * (b1.y + b1.x));
    float2 d2 = make_float2(-b2.y, b2.x);
    float2 d3 = make_float2(RSQ2 * (-(b3.x + b3.y)), RSQ2 * (b3.x - b3.y));
    float2 e0 = cadd(d0, d2), ee1 = csub(d0, d2), e2 = cadd(d1, d3), e3 = csub(d1, d3);
    float2 X1 = cadd(e0, e2), X5 = csub(e0, e2);
    float2 X3 = make_float2(ee1.x - e3.y, ee1.y + e3.x);
    float2 X7 = make_float2(ee1.x + e3.y, ee1.y - e3.x);

    if (LAST) {
        R[base]         = X0.x;
        R[base + h]     = X1.x;
        R[base + 2 * h] = X2.x;
        R[base + 3 * h] = X3.x;
        R[base + 4 * h] = X4.x;
        R[base + 5 * h] = X5.x;
        R[base + 6 * h] = X6.x;
        R[base + 7 * h] = X7.x;
    } else {
        A[PAD(base)]         = X0;
        A[PAD(base + h)]     = X1;
        A[PAD(base + 2 * h)] = X2;
        A[PAD(base + 3 * h)] = X3;
        A[PAD(base + 4 * h)] = X4;
        A[PAD(base + 5 * h)] = X5;
        A[PAD(base + 6 * h)] = X6;
        A[PAD(base + 7 * h)] = X7;
    }
}

__global__ __launch_bounds__(THREADS, 4) void tdi_kernel(const float* __restrict__ pr,
                                                         const float* __restrict__ pi,
                                                         float4* __restrict__ out,
                                                         long long n0, long long n1,
                                                         long long cap_f4)
{
    extern __shared__ float2 sh[];
    float2* Tb = sh;                    // 256 entries
    float2* Y0 = sh + 256;
    float2* Y1 = sh + 2560;
    float*  R0 = (float*)(sh + 4864);   // 2048 floats
    float*  R1 = R0 + 2048;             // 2048 floats

    const int tid = threadIdx.x;
    const int b   = blockIdx.x;
    const long long base = (long long)b * 4096;

    // Tb[m] = e^{+2*pi*i*m/2048}, m in [0,256)
    {
        float s, c;
        __sincosf((float)tid * 3.0679615757712823e-3f, &s, &c);
        Tb[tid] = make_float2(c, s);
    }
    for (int n = tid; n < 2048; n += THREADS) {
        long long i0 = base + n;
        long long i1 = base + n + 2048;
        float r0 = (i0 < n0) ? pr[i0] : 0.0f;
        float m0 = (i0 < n1) ? pi[i0] : 0.0f;
        float r1 = (i1 < n0) ? pr[i1] : 0.0f;
        float m1 = (i1 < n1) ? pi[i1] : 0.0f;
        Y0[PAD(n)] = make_float2(r0, m0);
        Y1[PAD(n)] = make_float2(r1, m1);
    }
    __syncthreads();

    // each thread does butterfly tid on BOTH arrays (256 butterflies per array per stage)
    // forward radix-8 DIF: h = 256, 32, 4
    fwd8(Y0, Tb, tid, 256, 1);  fwd8(Y1, Tb, tid, 256, 1);  __syncthreads();
    fwd8(Y0, Tb, tid, 32,  8);  fwd8(Y1, Tb, tid, 32,  8);  __syncthreads();
    fwd8(Y0, Tb, tid, 4,   64); fwd8(Y1, Tb, tid, 4,   64); __syncthreads();

    // fused middle: forward radix-4 (L=4) + pointwise w/2048 + inverse radix-4
    #pragma unroll
    for (int it = 0; it < 2; it++) {
        int m = tid + it * THREADS;                         // quad index in [0,512)
        int revm = ((m & 7) << 6) | (m & 56) | (m >> 6);    // 3-octal-digit reverse
        float sn, cs;
        __sincosf((float)revm * 1.5339807878856412e-3f, &sn, &cs);   // 2*pi/4096
        float2 w0 = make_float2(cs * (1.0f / 2048.0f), sn * (1.0f / 2048.0f));
        float2 wA = make_float2(RSQ2 * (w0.x - w0.y), RSQ2 * (w0.x + w0.y));
        float2 wB = make_float2(w0.y, -w0.x);
        float2 wC = make_float2(RSQ2 * (w0.x + w0.y), RSQ2 * (w0.y - w0.x));
        int p = 4 * m;
        #pragma unroll
        for (int s = 0; s < 2; s++) {
            float2* A = s ? Y1 : Y0;
            float2 t0 = A[PAD(p)],     t1 = A[PAD(p + 1)];
            float2 t2 = A[PAD(p + 2)], t3 = A[PAD(p + 3)];
            float2 a = cadd(t0, t2), bb = csub(t0, t2);
            float2 c = cadd(t1, t3), d  = csub(t1, t3);
            float2 F0 = cadd(a, c);
            float2 F1 = make_float2(bb.x + d.y, bb.y - d.x);
            float2 F2 = csub(a, c);
            float2 F3 = make_float2(bb.x - d.y, bb.y + d.x);
            float2 G0 = cmul(F0, w0), G1 = cmul(F1, wA);
            float2 G2 = cmul(F2, wB), G3 = cmul(F3, wC);
            float2 ap = cadd(G0, G2), bp = csub(G0, G2);
            float2 cp = cadd(G1, G3), dp = csub(G1, G3);
            A[PAD(p)]     = cadd(ap, cp);
            A[PAD(p + 2)] = csub(ap, cp);
            A[PAD(p + 1)] = make_float2(bp.x - dp.y, bp.y + dp.x);
            A[PAD(p + 3)] = make_float2(bp.x + dp.y, bp.y - dp.x);
        }
    }
    __syncthreads();

    // inverse radix-8 DIT: h = 4, 32, 256 (last writes real-only)
    inv8<false>(Y0, R0, Tb, tid, 4,   64); inv8<false>(Y1, R1, Tb, tid, 4,   64); __syncthreads();
    inv8<false>(Y0, R0, Tb, tid, 32,  8);  inv8<false>(Y1, R1, Tb, tid, 32,  8);  __syncthreads();
    inv8<true> (Y0, R0, Tb, tid, 256, 1);  inv8<true> (Y1, R1, Tb, tid, 256, 1);  __syncthreads();

    // output: real parts, [b][t][sc]; one float4 covers sc {4u..4u+3}
    const long long obf4 = (long long)b * (NT * NSC / 4);
    const bool ok = (obf4 + (long long)NT * (NSC / 4)) <= cap_f4
                 && (base + 4096) <= n0;
    const float2* R0v = (const float2*)R0;
    const float2* R1v = (const float2*)R1;
    for (int u = tid; u < 1024; u += THREADS) {
        int ra = 2 * u, rb = 2 * u + 1;
        float2 o0 = R0v[u];       // {R0[2u], R0[2u+1]}
        float2 o1 = R1v[u];
        if (ok) {
            float ea0 = pr[base + ra], ea1 = pr[base + ra + 2048];
            float eb0 = pr[base + rb], eb1 = pr[base + rb + 2048];
            #pragma unroll
            for (int t = 0; t < NT; t++) {
                float w = c_w[t];
                float4 v;
                v.x = ea0 + (ea1 - ea0) * w;
                v.y = o0.x + (o1.x - o0.x) * w;
                v.z = eb0 + (eb1 - eb0) * w;
                v.w = o0.y + (o1.y - o0.y) * w;
                out[obf4 + (long long)t * (NSC / 4) + u] = v;
            }
        } else {
            float ea0 = (base + ra < n0) ? pr[base + ra] : 0.0f;
            float ea1 = (base + ra + 2048 < n0) ? pr[base + ra + 2048] : 0.0f;
            float eb0 = (base + rb < n0) ? pr[base + rb] : 0.0f;
            float eb1 = (base + rb + 2048 < n0) ? pr[base + rb + 2048] : 0.0f;
            #pragma unroll
            for (int t = 0; t < NT; t++) {
                float w = c_w[t];
                long long f4 = obf4 + (long long)t * (NSC / 4) + u;
                if (f4 < cap_f4) {
                    float4 v;
                    v.x = ea0 + (ea1 - ea0) * w;
                    v.y = o0.x + (o1.x - o0.x) * w;
                    v.z = eb0 + (eb1 - eb0) * w;
                    v.w = o0.y + (o1.y - o0.y) * w;
                    out[f4] = v;
                }
            }
        }
    }
}

extern "C" void kernel_launch(void* const* d_in, const int* in_sizes, int n_in,
                              void* d_out, int out_size) {
    const float* pr = (const float*)d_in[0];
    const int ilast = (n_in > 1) ? (n_in - 1) : 0;
    const float* pi = (const float*)d_in[ilast];

    const long long n0 = (long long)in_sizes[0];
    const long long n1 = (long long)in_sizes[ilast];

    long long B = n0 / 4096;
    long long B_cap = (long long)out_size / ((long long)NT * NSC);
    if (B_cap < B) B = B_cap;
    if (B < 1) B = 1;
    if (B > 65535) B = 65535;

    const long long cap_f4 = (long long)out_size / 4;

    static bool attr_done = false;
    if (!attr_done) {
        cudaFuncSetAttribute(tdi_kernel, cudaFuncAttributeMaxDynamicSharedMemorySize, SMEM_BYTES);
        attr_done = true;
    }
    tdi_kernel<<<(int)B, THREADS, SMEM_BYTES>>>(pr, pi, (float4*)d_out, n0, n1, cap_f4);
}